// round 8
// baseline (speedup 1.0000x reference)
#include <cuda_runtime.h>

#define EMBED 1024
#define NHEAD 16
#define HDIM  64
#define BB    2
#define NSEQ  2048

// ---- device scratch (static: allocation rules forbid cudaMalloc) ----
__device__ float g_Q[BB*NHEAD*NSEQ*HDIM];     // 16 MB
__device__ float g_K[BB*NHEAD*NSEQ*HDIM];     // 16 MB
__device__ float g_V[BB*NHEAD*NSEQ*HDIM];     // 16 MB
__device__ float g_attn[BB*NSEQ*EMBED];       // 16 MB  [B,N,C] with C = h*64+d

// ============================================================
// Kernel 1: QKV GEMM  [4096,1024] @ [1024,3072] + bias
// 128x128x16 tiles, 256 threads, 8x8 microtile.
// Double-buffered smem + vectorized LDS.128 operand reads.
// Epilogue scatters into g_Q/g_K/g_V in [B,H,N,D] layout.
// ============================================================
__global__ __launch_bounds__(256) void qkv_gemm_kernel(
    const float* __restrict__ X, const float* __restrict__ W,
    const float* __restrict__ bias)
{
    const int K = EMBED;       // 1024
    const int N = 3 * EMBED;   // 3072
    __shared__ float As[2][16][132];   // A^T tile (k-major), padded
    __shared__ float Bs[2][16][128];

    int tid = threadIdx.x;
    int bm = blockIdx.y * 128;
    int bn = blockIdx.x * 128;
    int ty = tid >> 4, tx = tid & 15;

    // per-thread load coords (2 float4 slots each for A and B parts)
    int mA0 = tid >> 1;                 // lin = tid      : m = lin>>2 ... recompute generically
    (void)mA0;

    float acc[8][8];
#pragma unroll
    for (int i = 0; i < 8; i++)
#pragma unroll
        for (int j = 0; j < 8; j++) acc[i][j] = 0.f;

    // ---- preload tile 0 into buffer 0 ----
    {
        int k0 = 0;
#pragma unroll
        for (int s = 0; s < 2; s++) {
            int lin = tid + s * 256;
            int m  = lin >> 2;
            int k4 = (lin & 3) << 2;
            float4 v = *(const float4*)(X + (size_t)(bm + m) * K + k0 + k4);
            As[0][k4 + 0][m] = v.x; As[0][k4 + 1][m] = v.y;
            As[0][k4 + 2][m] = v.z; As[0][k4 + 3][m] = v.w;
            int kk = lin >> 5;
            int n4 = (lin & 31) << 2;
            *(float4*)&Bs[0][kk][n4] =
                *(const float4*)(W + (size_t)(k0 + kk) * N + bn + n4);
        }
    }
    __syncthreads();

    const int T = K / 16;  // 64 tiles
    for (int t = 0; t < T; t++) {
        float4 xv[2], wv[2];
        bool has = (t + 1) < T;
        if (has) {
            int k0 = (t + 1) * 16;
#pragma unroll
            for (int s = 0; s < 2; s++) {
                int lin = tid + s * 256;
                int m  = lin >> 2;
                int k4 = (lin & 3) << 2;
                xv[s] = *(const float4*)(X + (size_t)(bm + m) * K + k0 + k4);
                int kk = lin >> 5;
                int n4 = (lin & 31) << 2;
                wv[s] = *(const float4*)(W + (size_t)(k0 + kk) * N + bn + n4);
            }
        }

        int p = t & 1;
#pragma unroll
        for (int kk = 0; kk < 16; kk++) {
            float4 a0 = *(const float4*)&As[p][kk][ty * 8];
            float4 a1 = *(const float4*)&As[p][kk][ty * 8 + 4];
            float4 b0 = *(const float4*)&Bs[p][kk][tx * 8];
            float4 b1 = *(const float4*)&Bs[p][kk][tx * 8 + 4];
            float a[8] = {a0.x, a0.y, a0.z, a0.w, a1.x, a1.y, a1.z, a1.w};
            float b[8] = {b0.x, b0.y, b0.z, b0.w, b1.x, b1.y, b1.z, b1.w};
#pragma unroll
            for (int i = 0; i < 8; i++)
#pragma unroll
                for (int j = 0; j < 8; j++)
                    acc[i][j] = fmaf(a[i], b[j], acc[i][j]);
        }

        if (has) {
            int q = p ^ 1;
#pragma unroll
            for (int s = 0; s < 2; s++) {
                int lin = tid + s * 256;
                int m  = lin >> 2;
                int k4 = (lin & 3) << 2;
                As[q][k4 + 0][m] = xv[s].x; As[q][k4 + 1][m] = xv[s].y;
                As[q][k4 + 2][m] = xv[s].z; As[q][k4 + 3][m] = xv[s].w;
                int kk = lin >> 5;
                int n4 = (lin & 31) << 2;
                *(float4*)&Bs[q][kk][n4] = wv[s];
            }
        }
        __syncthreads();
    }

    // epilogue: add bias, scatter into Q/K/V [B,H,N,D]
#pragma unroll
    for (int i = 0; i < 8; i++) {
        int row = bm + ty * 8 + i;       // 0..4095
        int b = row >> 11;               // /2048
        int n = row & 2047;
#pragma unroll
        for (int j = 0; j < 8; j++) {
            int col = bn + tx * 8 + j;   // 0..3071
            float v = acc[i][j] + bias[col];
            int t = col >> 10;
            int h = (col >> 6) & 15;
            int d = col & 63;
            size_t idx = ((size_t)(b * NHEAD + h) * NSEQ + n) * HDIM + d;
            if (t == 0)      g_Q[idx] = v;
            else if (t == 1) g_K[idx] = v;
            else             g_V[idx] = v;
        }
    }
}

// ============================================================
// Kernel 2: flash attention per (b,h). BM=64 queries, BN=64 keys.
// 256 threads: ty=tid/16 (4 q-rows), tx=tid%16 (4 k-cols / 4 dims).
// float4 LDS over d with xor chunk swizzle (conflict avoidance).
// P tile aliases the K smem buffer. 48KB static smem exactly.
// ============================================================
__global__ __launch_bounds__(256) void flash_kernel()
{
    __shared__ float sm[3 * 64 * 64];       // 48 KB
    float* Qs = sm;                         // swizzled [64][16 f4-chunks]
    float* Ks = sm + 4096;                  // swizzled; aliased as P (row-major)
    float* Vs = sm + 8192;                  // row-major [64][64]

    int tid = threadIdx.x;
    int bh  = blockIdx.y;                   // 0..31 = b*16+h
    int q0  = blockIdx.x * 64;
    size_t base = (size_t)bh * NSEQ * HDIM;
    int ty = tid >> 4;      // 0..15
    int tx = tid & 15;      // 0..15

    const float scale = 0.125f;   // 64^-0.5

    // load Q tile (swizzled), pre-scaled
#pragma unroll
    for (int s = 0; s < 4; s++) {
        int lin = tid + s * 256;            // float4 units, 0..1023
        int r = lin >> 4, m = lin & 15;
        float4 v = *(const float4*)(g_Q + base + (size_t)(q0 + r) * HDIM + 4 * m);
        v.x *= scale; v.y *= scale; v.z *= scale; v.w *= scale;
        int pc = m ^ ((r >> 2) & 15);
        *(float4*)(Qs + r * 64 + pc * 4) = v;
    }

    float m_i[4], l_i[4];
    float4 acc[4];
#pragma unroll
    for (int i = 0; i < 4; i++) {
        m_i[i] = -1e30f; l_i[i] = 0.f;
        acc[i] = make_float4(0.f, 0.f, 0.f, 0.f);
    }

    for (int kt = 0; kt < NSEQ; kt += 64) {
        __syncthreads();   // prior iter done reading Ks(P)/Vs; Q visible (1st)
#pragma unroll
        for (int s = 0; s < 4; s++) {
            int lin = tid + s * 256;
            int r = lin >> 4, m = lin & 15;
            float4 kv = *(const float4*)(g_K + base + (size_t)(kt + r) * HDIM + 4 * m);
            int pc = m ^ ((r >> 2) & 15);
            *(float4*)(Ks + r * 64 + pc * 4) = kv;
            float4 vv = *(const float4*)(g_V + base + (size_t)(kt + r) * HDIM + 4 * m);
            *(float4*)(Vs + r * 64 + m * 4) = vv;
        }
        __syncthreads();

        // S = Q K^T (scaled) : dot over d via float4 chunks
        float s4[4][4];
#pragma unroll
        for (int i = 0; i < 4; i++)
#pragma unroll
            for (int j = 0; j < 4; j++) s4[i][j] = 0.f;

#pragma unroll
        for (int s = 0; s < 16; s++) {
            float4 qa[4], kb[4];
#pragma unroll
            for (int i = 0; i < 4; i++)
                qa[i] = *(const float4*)(Qs + (ty * 4 + i) * 64 + ((s ^ ty) & 15) * 4);
#pragma unroll
            for (int j = 0; j < 4; j++)
                kb[j] = *(const float4*)(Ks + (tx * 4 + j) * 64 + ((s ^ tx) & 15) * 4);
#pragma unroll
            for (int i = 0; i < 4; i++)
#pragma unroll
                for (int j = 0; j < 4; j++) {
                    s4[i][j] = fmaf(qa[i].x, kb[j].x, s4[i][j]);
                    s4[i][j] = fmaf(qa[i].y, kb[j].y, s4[i][j]);
                    s4[i][j] = fmaf(qa[i].z, kb[j].z, s4[i][j]);
                    s4[i][j] = fmaf(qa[i].w, kb[j].w, s4[i][j]);
                }
        }

        // per-row max across the 16-lane tx group
        float mt[4];
#pragma unroll
        for (int i = 0; i < 4; i++) {
            mt[i] = s4[i][0];
#pragma unroll
            for (int j = 1; j < 4; j++) mt[i] = fmaxf(mt[i], s4[i][j]);
        }
#pragma unroll
        for (int off = 8; off >= 1; off >>= 1)
#pragma unroll
            for (int i = 0; i < 4; i++)
                mt[i] = fmaxf(mt[i], __shfl_xor_sync(0xffffffffu, mt[i], off));

        float p[4][4], ps[4], alpha[4];
#pragma unroll
        for (int i = 0; i < 4; i++) {
            float mnew = fmaxf(m_i[i], mt[i]);
            alpha[i] = __expf(m_i[i] - mnew);
            m_i[i] = mnew;
            ps[i] = 0.f;
#pragma unroll
            for (int j = 0; j < 4; j++) {
                p[i][j] = __expf(s4[i][j] - mnew);
                ps[i] += p[i][j];
            }
        }
#pragma unroll
        for (int off = 8; off >= 1; off >>= 1)
#pragma unroll
            for (int i = 0; i < 4; i++)
                ps[i] += __shfl_xor_sync(0xffffffffu, ps[i], off);
#pragma unroll
        for (int i = 0; i < 4; i++) {
            l_i[i] = l_i[i] * alpha[i] + ps[i];
            acc[i].x *= alpha[i]; acc[i].y *= alpha[i];
            acc[i].z *= alpha[i]; acc[i].w *= alpha[i];
        }

        __syncthreads();   // everyone done reading K tile
        // write P row-major into the K buffer: P[r][c] at Ks[r*64 + c]
#pragma unroll
        for (int i = 0; i < 4; i++)
            *(float4*)(Ks + (ty * 4 + i) * 64 + tx * 4) =
                make_float4(p[i][0], p[i][1], p[i][2], p[i][3]);
        __syncthreads();

        // O += P @ V  (thread owns d-cols 4tx..4tx+3)
#pragma unroll
        for (int c4 = 0; c4 < 16; c4++) {
            float4 pc[4], vv[4];
#pragma unroll
            for (int i = 0; i < 4; i++)
                pc[i] = *(const float4*)(Ks + (ty * 4 + i) * 64 + c4 * 4);
#pragma unroll
            for (int jc = 0; jc < 4; jc++)
                vv[jc] = *(const float4*)(Vs + (c4 * 4 + jc) * 64 + tx * 4);
#pragma unroll
            for (int i = 0; i < 4; i++) {
                acc[i].x = fmaf(pc[i].x, vv[0].x, acc[i].x);
                acc[i].y = fmaf(pc[i].x, vv[0].y, acc[i].y);
                acc[i].z = fmaf(pc[i].x, vv[0].z, acc[i].z);
                acc[i].w = fmaf(pc[i].x, vv[0].w, acc[i].w);
                acc[i].x = fmaf(pc[i].y, vv[1].x, acc[i].x);
                acc[i].y = fmaf(pc[i].y, vv[1].y, acc[i].y);
                acc[i].z = fmaf(pc[i].y, vv[1].z, acc[i].z);
                acc[i].w = fmaf(pc[i].y, vv[1].w, acc[i].w);
                acc[i].x = fmaf(pc[i].z, vv[2].x, acc[i].x);
                acc[i].y = fmaf(pc[i].z, vv[2].y, acc[i].y);
                acc[i].z = fmaf(pc[i].z, vv[2].z, acc[i].z);
                acc[i].w = fmaf(pc[i].z, vv[2].w, acc[i].w);
                acc[i].x = fmaf(pc[i].w, vv[3].x, acc[i].x);
                acc[i].y = fmaf(pc[i].w, vv[3].y, acc[i].y);
                acc[i].z = fmaf(pc[i].w, vv[3].z, acc[i].z);
                acc[i].w = fmaf(pc[i].w, vv[3].w, acc[i].w);
            }
        }
    }

    // epilogue: normalize, write [B,N,C] with C = h*64 + d
    int b = bh >> 4, h = bh & 15;
#pragma unroll
    for (int i = 0; i < 4; i++) {
        int n = q0 + ty * 4 + i;
        float inv = 1.f / l_i[i];
        float4 o;
        o.x = acc[i].x * inv; o.y = acc[i].y * inv;
        o.z = acc[i].z * inv; o.w = acc[i].w * inv;
        *(float4*)&g_attn[((size_t)(b * NSEQ + n)) * EMBED + h * 64 + tx * 4] = o;
    }
}

// ============================================================
// Kernel 3: output projection  [4096,1024] @ [1024,1024] + bias
// Same double-buffered SGEMM, plain epilogue to d_out.
// ============================================================
__global__ __launch_bounds__(256) void proj_gemm_kernel(
    const float* __restrict__ W, const float* __restrict__ bias,
    float* __restrict__ Out)
{
    const int K = EMBED;       // 1024
    const int N = EMBED;       // 1024
    __shared__ float As[2][16][132];
    __shared__ float Bs[2][16][128];

    int tid = threadIdx.x;
    int bm = blockIdx.y * 128;
    int bn = blockIdx.x * 128;
    int ty = tid >> 4, tx = tid & 15;

    float acc[8][8];
#pragma unroll
    for (int i = 0; i < 8; i++)
#pragma unroll
        for (int j = 0; j < 8; j++) acc[i][j] = 0.f;

    {
        int k0 = 0;
#pragma unroll
        for (int s = 0; s < 2; s++) {
            int lin = tid + s * 256;
            int m  = lin >> 2;
            int k4 = (lin & 3) << 2;
            float4 v = *(const float4*)(g_attn + (size_t)(bm + m) * K + k0 + k4);
            As[0][k4 + 0][m] = v.x; As[0][k4 + 1][m] = v.y;
            As[0][k4 + 2][m] = v.z; As[0][k4 + 3][m] = v.w;
            int kk = lin >> 5;
            int n4 = (lin & 31) << 2;
            *(float4*)&Bs[0][kk][n4] =
                *(const float4*)(W + (size_t)(k0 + kk) * N + bn + n4);
        }
    }
    __syncthreads();

    const int T = K / 16;
    for (int t = 0; t < T; t++) {
        float4 xv[2], wv[2];
        bool has = (t + 1) < T;
        if (has) {
            int k0 = (t + 1) * 16;
#pragma unroll
            for (int s = 0; s < 2; s++) {
                int lin = tid + s * 256;
                int m  = lin >> 2;
                int k4 = (lin & 3) << 2;
                xv[s] = *(const float4*)(g_attn + (size_t)(bm + m) * K + k0 + k4);
                int kk = lin >> 5;
                int n4 = (lin & 31) << 2;
                wv[s] = *(const float4*)(W + (size_t)(k0 + kk) * N + bn + n4);
            }
        }

        int p = t & 1;
#pragma unroll
        for (int kk = 0; kk < 16; kk++) {
            float4 a0 = *(const float4*)&As[p][kk][ty * 8];
            float4 a1 = *(const float4*)&As[p][kk][ty * 8 + 4];
            float4 b0 = *(const float4*)&Bs[p][kk][tx * 8];
            float4 b1 = *(const float4*)&Bs[p][kk][tx * 8 + 4];
            float a[8] = {a0.x, a0.y, a0.z, a0.w, a1.x, a1.y, a1.z, a1.w};
            float b[8] = {b0.x, b0.y, b0.z, b0.w, b1.x, b1.y, b1.z, b1.w};
#pragma unroll
            for (int i = 0; i < 8; i++)
#pragma unroll
                for (int j = 0; j < 8; j++)
                    acc[i][j] = fmaf(a[i], b[j], acc[i][j]);
        }

        if (has) {
            int q = p ^ 1;
#pragma unroll
            for (int s = 0; s < 2; s++) {
                int lin = tid + s * 256;
                int m  = lin >> 2;
                int k4 = (lin & 3) << 2;
                As[q][k4 + 0][m] = xv[s].x; As[q][k4 + 1][m] = xv[s].y;
                As[q][k4 + 2][m] = xv[s].z; As[q][k4 + 3][m] = xv[s].w;
                int kk = lin >> 5;
                int n4 = (lin & 31) << 2;
                *(float4*)&Bs[q][kk][n4] = wv[s];
            }
        }
        __syncthreads();
    }

#pragma unroll
    for (int i = 0; i < 8; i++) {
        int row = bm + ty * 8 + i;
#pragma unroll
        for (int j4 = 0; j4 < 2; j4++) {
            int col = bn + tx * 8 + j4 * 4;
            float4 bb = *(const float4*)&bias[col];
            float4 o;
            o.x = acc[i][j4 * 4 + 0] + bb.x;
            o.y = acc[i][j4 * 4 + 1] + bb.y;
            o.z = acc[i][j4 * 4 + 2] + bb.z;
            o.w = acc[i][j4 * 4 + 3] + bb.w;
            *(float4*)&Out[(size_t)row * N + col] = o;
        }
    }
}

// ============================================================
extern "C" void kernel_launch(void* const* d_in, const int* in_sizes, int n_in,
                              void* d_out, int out_size)
{
    const float* x     = (const float*)d_in[0];  // [2,2048,1024]
    const float* W_qkv = (const float*)d_in[1];  // [1024,3072]
    const float* b_qkv = (const float*)d_in[2];  // [3072]
    const float* W_p   = (const float*)d_in[3];  // [1024,1024]
    const float* b_p   = (const float*)d_in[4];  // [1024]
    float* out = (float*)d_out;                  // [2,2048,1024]

    qkv_gemm_kernel<<<dim3(24, 32), 256>>>(x, W_qkv, b_qkv);
    flash_kernel<<<dim3(32, 32), 256>>>();
    proj_gemm_kernel<<<dim3(8, 32), 256>>>(W_p, b_p, out);
}

// round 13
// speedup vs baseline: 1.5754x; 1.5754x over previous
#include <cuda_runtime.h>

#define EMBED 1024
#define NHEAD 16
#define HDIM  64
#define BB    2
#define NSEQ  2048

// ---- device scratch (static: allocation rules forbid cudaMalloc) ----
__device__ float g_Q[BB*NHEAD*NSEQ*HDIM];     // 16 MB
__device__ float g_K[BB*NHEAD*NSEQ*HDIM];     // 16 MB
__device__ float g_V[BB*NHEAD*NSEQ*HDIM];     // 16 MB
__device__ float g_attn[BB*NSEQ*EMBED];       // 16 MB  [B,N,C] with C = h*64+d

// ---- packed f32x2 helpers (SASS FFMA2 path; ptxas never emits from C++) ----
__device__ __forceinline__ unsigned long long pack2(float x) {
    unsigned long long r;
    asm("mov.b64 %0, {%1, %1};" : "=l"(r) : "f"(x));
    return r;
}
__device__ __forceinline__ unsigned long long packf2(float lo, float hi) {
    unsigned long long r;
    asm("mov.b64 %0, {%1, %2};" : "=l"(r) : "f"(lo), "f"(hi));
    return r;
}
__device__ __forceinline__ void ffma2(unsigned long long& d,
                                      unsigned long long a,
                                      unsigned long long b) {
    asm("fma.rn.f32x2 %0, %1, %2, %0;" : "+l"(d) : "l"(a), "l"(b));
}
__device__ __forceinline__ void fmul2(unsigned long long& d,
                                      unsigned long long a,
                                      unsigned long long b) {
    asm("mul.rn.f32x2 %0, %1, %2;" : "=l"(d) : "l"(a), "l"(b));
}
__device__ __forceinline__ float2 unpack2(unsigned long long v) {
    float lo, hi;
    asm("mov.b64 {%0, %1}, %2;" : "=f"(lo), "=f"(hi) : "l"(v));
    return make_float2(lo, hi);
}

// ============================================================
// Kernel 1: QKV GEMM  [4096,1024] @ [1024,3072] + bias
// 128x128x16 tiles, 256 threads, 8x8 microtile, FFMA2 core.
// Epilogue scatters into g_Q/g_K/g_V in [B,H,N,D] layout.
// ============================================================
__global__ __launch_bounds__(256) void qkv_gemm_kernel(
    const float* __restrict__ X, const float* __restrict__ W,
    const float* __restrict__ bias)
{
    const int K = EMBED;       // 1024
    const int N = 3 * EMBED;   // 3072
    __shared__ __align__(16) float As[16][132];   // A^T tile (k-major), padded
    __shared__ __align__(16) float Bs[16][128];

    int tid = threadIdx.x;
    int bm = blockIdx.y * 128;
    int bn = blockIdx.x * 128;
    int ty = tid >> 4, tx = tid & 15;

    unsigned long long acc2[8][4];
#pragma unroll
    for (int i = 0; i < 8; i++)
#pragma unroll
        for (int j = 0; j < 4; j++) acc2[i][j] = 0ull;

    for (int k0 = 0; k0 < K; k0 += 16) {
#pragma unroll
        for (int s = 0; s < 2; s++) {
            int lin = tid + s * 256;             // 0..511 float4 slots
            int m  = lin >> 2;
            int k4 = (lin & 3) << 2;
            float4 v = *(const float4*)(X + (size_t)(bm + m) * K + k0 + k4);
            As[k4 + 0][m] = v.x; As[k4 + 1][m] = v.y;
            As[k4 + 2][m] = v.z; As[k4 + 3][m] = v.w;
            int kk = lin >> 5;
            int n4 = (lin & 31) << 2;
            *(float4*)&Bs[kk][n4] =
                *(const float4*)(W + (size_t)(k0 + kk) * N + bn + n4);
        }
        __syncthreads();
#pragma unroll
        for (int kk = 0; kk < 16; kk++) {
            float4 a0 = *(const float4*)&As[kk][ty * 8];
            float4 a1 = *(const float4*)&As[kk][ty * 8 + 4];
            ulonglong2 b0 = *(const ulonglong2*)&Bs[kk][tx * 8];
            ulonglong2 b1 = *(const ulonglong2*)&Bs[kk][tx * 8 + 4];
            unsigned long long bp[4] = {b0.x, b0.y, b1.x, b1.y};
            float av[8] = {a0.x, a0.y, a0.z, a0.w, a1.x, a1.y, a1.z, a1.w};
#pragma unroll
            for (int i = 0; i < 8; i++) {
                unsigned long long ai = pack2(av[i]);
#pragma unroll
                for (int j = 0; j < 4; j++) ffma2(acc2[i][j], ai, bp[j]);
            }
        }
        __syncthreads();
    }

    // epilogue: add bias, scatter into Q/K/V [B,H,N,D]
#pragma unroll
    for (int i = 0; i < 8; i++) {
        int row = bm + ty * 8 + i;       // 0..4095
        int b = row >> 11;               // /2048
        int n = row & 2047;
#pragma unroll
        for (int j4 = 0; j4 < 4; j4++) {
            float2 t = unpack2(acc2[i][j4]);
#pragma unroll
            for (int e = 0; e < 2; e++) {
                int col = bn + tx * 8 + 2 * j4 + e;   // 0..3071
                float v = (e ? t.y : t.x) + bias[col];
                int ttt = col >> 10;
                int h = (col >> 6) & 15;
                int d = col & 63;
                size_t idx = ((size_t)(b * NHEAD + h) * NSEQ + n) * HDIM + d;
                if (ttt == 0)      g_Q[idx] = v;
                else if (ttt == 1) g_K[idx] = v;
                else               g_V[idx] = v;
            }
        }
    }
}

// ============================================================
// Kernel 2: flash attention per (b,h). BM=32 queries, BN=64 keys.
// 128 threads: ty=tid/16 (4 q-rows ty*4+i), tx=tid%16 (k-cols tx+16j).
// Q/K stored as f32x2 d-pair tiles, transposed: Qp[d2][row], Kp[d2][col].
// S and PV inner products use fma.rn.f32x2 (FFMA2).
// ============================================================
__global__ __launch_bounds__(128) void flash_kernel()
{
    __shared__ unsigned long long Qp[32][32];     // 8 KB  [d2][q-row]
    __shared__ unsigned long long Kp[32][64];     // 16 KB [d2][k-col]
    __shared__ __align__(16) float Vs[64][64];    // 16 KB row-major
    __shared__ float Ps[32][64];                  // 8 KB  P[q-row][k-col]

    int tid = threadIdx.x;
    int bh  = blockIdx.y;                   // 0..31 = b*16+h
    int q0  = blockIdx.x * 32;
    size_t base = (size_t)bh * NSEQ * HDIM;
    int ty = tid >> 4;      // 0..7
    int tx = tid & 15;      // 0..15

    const float scale = 0.125f;   // 64^-0.5

    // load Q tile -> transposed d-pair layout (pre-scaled), once per block
#pragma unroll
    for (int s = 0; s < 4; s++) {
        int lin = tid + s * 128;            // 0..511 float4 units
        int r = lin & 31;
        int m = (lin >> 5) & 15;
        float4 v = *(const float4*)(g_Q + base + (size_t)(q0 + r) * HDIM + 4 * m);
        Qp[2 * m][r]     = packf2(v.x * scale, v.y * scale);
        Qp[2 * m + 1][r] = packf2(v.z * scale, v.w * scale);
    }

    float m_i[4], l_i[4];
    unsigned long long o2[4][2];        // packed output acc: d = 4tx..4tx+3
#pragma unroll
    for (int i = 0; i < 4; i++) {
        m_i[i] = -1e30f; l_i[i] = 0.f;
        o2[i][0] = 0ull; o2[i][1] = 0ull;
    }

    for (int kt = 0; kt < NSEQ; kt += 64) {
        __syncthreads();   // prior iter done reading Kp/Vs/Ps; Q visible (1st)
        // K -> transposed d-pair layout (r-major lane map: 2-way store conflicts)
#pragma unroll
        for (int s = 0; s < 8; s++) {
            int lin = tid + s * 128;        // 0..1023 float4 units
            int r = lin & 63;
            int m = (lin >> 6) & 15;
            float4 kv = *(const float4*)(g_K + base + (size_t)(kt + r) * HDIM + 4 * m);
            Kp[2 * m][r]     = packf2(kv.x, kv.y);
            Kp[2 * m + 1][r] = packf2(kv.z, kv.w);
        }
        // V row-major, coalesced
#pragma unroll
        for (int s = 0; s < 8; s++) {
            int lin = tid + s * 128;
            int r = lin >> 4;
            int m = lin & 15;
            *(float4*)&Vs[r][m * 4] =
                *(const float4*)(g_V + base + (size_t)(kt + r) * HDIM + 4 * m);
        }
        __syncthreads();

        // S = Q K^T : packed dot over d-pairs (16 FFMA2 + 8 LDS.64 per d2)
        unsigned long long s2[4][4];
#pragma unroll
        for (int i = 0; i < 4; i++)
#pragma unroll
            for (int j = 0; j < 4; j++) s2[i][j] = 0ull;

#pragma unroll 4
        for (int d2 = 0; d2 < 32; d2++) {
            unsigned long long qa[4], kb[4];
#pragma unroll
            for (int i = 0; i < 4; i++) qa[i] = Qp[d2][ty * 4 + i];      // broadcast
#pragma unroll
            for (int j = 0; j < 4; j++) kb[j] = Kp[d2][tx + 16 * j];     // conflict-free
#pragma unroll
            for (int i = 0; i < 4; i++)
#pragma unroll
                for (int j = 0; j < 4; j++) ffma2(s2[i][j], qa[i], kb[j]);
        }
        float s4[4][4];
#pragma unroll
        for (int i = 0; i < 4; i++)
#pragma unroll
            for (int j = 0; j < 4; j++) {
                float2 t = unpack2(s2[i][j]);
                s4[i][j] = t.x + t.y;
            }

        // per-row max across the 16-lane tx group
        float mt[4];
#pragma unroll
        for (int i = 0; i < 4; i++) {
            mt[i] = s4[i][0];
#pragma unroll
            for (int j = 1; j < 4; j++) mt[i] = fmaxf(mt[i], s4[i][j]);
        }
#pragma unroll
        for (int off = 8; off >= 1; off >>= 1)
#pragma unroll
            for (int i = 0; i < 4; i++)
                mt[i] = fmaxf(mt[i], __shfl_xor_sync(0xffffffffu, mt[i], off));

        float p[4][4], ps[4], alpha[4];
#pragma unroll
        for (int i = 0; i < 4; i++) {
            float mnew = fmaxf(m_i[i], mt[i]);
            alpha[i] = __expf(m_i[i] - mnew);
            m_i[i] = mnew;
            ps[i] = 0.f;
#pragma unroll
            for (int j = 0; j < 4; j++) {
                p[i][j] = __expf(s4[i][j] - mnew);
                ps[i] += p[i][j];
            }
        }
#pragma unroll
        for (int off = 8; off >= 1; off >>= 1)
#pragma unroll
            for (int i = 0; i < 4; i++)
                ps[i] += __shfl_xor_sync(0xffffffffu, ps[i], off);
#pragma unroll
        for (int i = 0; i < 4; i++) {
            l_i[i] = l_i[i] * alpha[i] + ps[i];
            unsigned long long al = pack2(alpha[i]);
            fmul2(o2[i][0], o2[i][0], al);
            fmul2(o2[i][1], o2[i][1], al);
        }

        // write P (row r written & read only by lanes of the same ty -> same warp)
#pragma unroll
        for (int i = 0; i < 4; i++)
#pragma unroll
            for (int j = 0; j < 4; j++)
                Ps[ty * 4 + i][tx + 16 * j] = p[i][j];
        __syncwarp();

        // O += P @ V  (thread owns d-cols 4tx..4tx+3, packed in pairs)
#pragma unroll 8
        for (int c = 0; c < 64; c++) {
            ulonglong2 vv = *(const ulonglong2*)&Vs[c][tx * 4];
#pragma unroll
            for (int i = 0; i < 4; i++) {
                unsigned long long pd = pack2(Ps[ty * 4 + i][c]);   // broadcast
                ffma2(o2[i][0], pd, vv.x);
                ffma2(o2[i][1], pd, vv.y);
            }
        }
    }

    // epilogue: normalize, write [B,N,C] with C = h*64 + d
    int b = bh >> 4, h = bh & 15;
#pragma unroll
    for (int i = 0; i < 4; i++) {
        int n = q0 + ty * 4 + i;
        float inv = 1.f / l_i[i];
        float2 t0 = unpack2(o2[i][0]);
        float2 t1 = unpack2(o2[i][1]);
        float4 o;
        o.x = t0.x * inv; o.y = t0.y * inv;
        o.z = t1.x * inv; o.w = t1.y * inv;
        *(float4*)&g_attn[((size_t)(b * NSEQ + n)) * EMBED + h * 64 + tx * 4] = o;
    }
}

// ============================================================
// Kernel 3: output projection  [4096,1024] @ [1024,1024] + bias
// Same FFMA2 SGEMM, plain epilogue to d_out.
// ============================================================
__global__ __launch_bounds__(256) void proj_gemm_kernel(
    const float* __restrict__ W, const float* __restrict__ bias,
    float* __restrict__ Out)
{
    const int K = EMBED;       // 1024
    const int N = EMBED;       // 1024
    __shared__ __align__(16) float As[16][132];
    __shared__ __align__(16) float Bs[16][128];

    int tid = threadIdx.x;
    int bm = blockIdx.y * 128;
    int bn = blockIdx.x * 128;
    int ty = tid >> 4, tx = tid & 15;

    unsigned long long acc2[8][4];
#pragma unroll
    for (int i = 0; i < 8; i++)
#pragma unroll
        for (int j = 0; j < 4; j++) acc2[i][j] = 0ull;

    for (int k0 = 0; k0 < K; k0 += 16) {
#pragma unroll
        for (int s = 0; s < 2; s++) {
            int lin = tid + s * 256;
            int m  = lin >> 2;
            int k4 = (lin & 3) << 2;
            float4 v = *(const float4*)(g_attn + (size_t)(bm + m) * K + k0 + k4);
            As[k4 + 0][m] = v.x; As[k4 + 1][m] = v.y;
            As[k4 + 2][m] = v.z; As[k4 + 3][m] = v.w;
            int kk = lin >> 5;
            int n4 = (lin & 31) << 2;
            *(float4*)&Bs[kk][n4] =
                *(const float4*)(W + (size_t)(k0 + kk) * N + bn + n4);
        }
        __syncthreads();
#pragma unroll
        for (int kk = 0; kk < 16; kk++) {
            float4 a0 = *(const float4*)&As[kk][ty * 8];
            float4 a1 = *(const float4*)&As[kk][ty * 8 + 4];
            ulonglong2 b0 = *(const ulonglong2*)&Bs[kk][tx * 8];
            ulonglong2 b1 = *(const ulonglong2*)&Bs[kk][tx * 8 + 4];
            unsigned long long bp[4] = {b0.x, b0.y, b1.x, b1.y};
            float av[8] = {a0.x, a0.y, a0.z, a0.w, a1.x, a1.y, a1.z, a1.w};
#pragma unroll
            for (int i = 0; i < 8; i++) {
                unsigned long long ai = pack2(av[i]);
#pragma unroll
                for (int j = 0; j < 4; j++) ffma2(acc2[i][j], ai, bp[j]);
            }
        }
        __syncthreads();
    }

#pragma unroll
    for (int i = 0; i < 8; i++) {
        int row = bm + ty * 8 + i;
#pragma unroll
        for (int h4 = 0; h4 < 2; h4++) {
            int col = bn + tx * 8 + h4 * 4;
            float4 bb = *(const float4*)&bias[col];
            float2 t0 = unpack2(acc2[i][h4 * 2 + 0]);
            float2 t1 = unpack2(acc2[i][h4 * 2 + 1]);
            float4 o;
            o.x = t0.x + bb.x; o.y = t0.y + bb.y;
            o.z = t1.x + bb.z; o.w = t1.y + bb.w;
            *(float4*)&Out[(size_t)row * N + col] = o;
        }
    }
}

// ============================================================
extern "C" void kernel_launch(void* const* d_in, const int* in_sizes, int n_in,
                              void* d_out, int out_size)
{
    const float* x     = (const float*)d_in[0];  // [2,2048,1024]
    const float* W_qkv = (const float*)d_in[1];  // [1024,3072]
    const float* b_qkv = (const float*)d_in[2];  // [3072]
    const float* W_p   = (const float*)d_in[3];  // [1024,1024]
    const float* b_p   = (const float*)d_in[4];  // [1024]
    float* out = (float*)d_out;                  // [2,2048,1024]

    qkv_gemm_kernel<<<dim3(24, 32), 256>>>(x, W_qkv, b_qkv);
    flash_kernel<<<dim3(64, 32), 128>>>();
    proj_gemm_kernel<<<dim3(8, 32), 256>>>(W_p, b_p, out);
}